// round 8
// baseline (speedup 1.0000x reference)
#include <cuda_runtime.h>

#define MAP_W  64
#define MAP_H  64
#define T_SIZE 64
#define NUM_CP 8
#define BATCH  128
#define XPB    4      // x-columns per block

__device__ __forceinline__ float ex2_approx(float x) {
    float r;
    asm("ex2.approx.f32 %0, %1;" : "=f"(r) : "f"(x));
    return r;
}

// Fused kernel: block = (b, group of 4 x columns). Threads 0..63 compute the
// per-(b,t) Gaussian params for all 64 t into shared memory (SoA layout so
// the consumer float4 loads are bank-conflict-free), then all 256 threads
// stream 4 * 64*64 (y,t) tiles of exp2 evaluations.
//
// exponent(dx,dy) = al*dx^2 + be*dx*dy + ga*dy^2 + f0  (log2 domain; f0
// includes log2 of the normalizer), output = exp2(exponent).
struct SoAParams {
    float mx[T_SIZE], my[T_SIZE], al[T_SIZE],
          be[T_SIZE], ga[T_SIZE], f0[T_SIZE];
};

__global__ __launch_bounds__(256, 6)
void map_kernel(const float* __restrict__ cp_means,
                const int*   __restrict__ num_cps,
                const float* __restrict__ cp_cov,
                float*       __restrict__ out) {
    __shared__ SoAParams sp;

    int x0  = blockIdx.x * XPB;                // 0,4,..,60
    int b   = blockIdx.y;                      // 0..127
    int tid = threadIdx.y * 16 + threadIdx.x;  // 0..255

    if (tid < T_SIZE) {
        int   t  = tid;
        float tf = (float)t * (1.0f / 63.0f);
        float u  = 1.0f - tf;
        int   n  = __ldg(num_cps + b) - 1;     // 2..7

        // Bernstein weights via de Casteljau (exact, register-resident).
        float w[NUM_CP];
        w[0] = 1.0f;
        #pragma unroll
        for (int k = 1; k < NUM_CP; ++k) w[k] = 0.0f;
        #pragma unroll
        for (int m = 1; m < NUM_CP; ++m) {
            if (m <= n) {
                #pragma unroll
                for (int k = NUM_CP - 1; k >= 1; --k)
                    w[k] = u * w[k] + tf * w[k - 1];
                w[0] = u * w[0];
            }
        }

        float mx = 0.f, my = 0.f, cxx = 0.f, cxy = 0.f, cyx = 0.f, cyy = 0.f;
        #pragma unroll
        for (int k = 0; k < NUM_CP; ++k) {
            float wk = w[k];
            float2 m = __ldg((const float2*)(cp_means + (k * BATCH + b) * 2));
            mx += wk * m.x;
            my += wk * m.y;
            float w2 = wk * wk;
            float4 cv = __ldg((const float4*)(cp_cov + (k * BATCH + b) * 4));
            cxx += w2 * cv.x;  cxy += w2 * cv.y;
            cyx += w2 * cv.z;  cyy += w2 * cv.w;
        }

        float det  = cxx * cyy - cxy * cyx;
        float invd = 1.0f / det;
        const float L = 1.4426950408889634f;   // log2(e)
        sp.mx[t] = mx;
        sp.my[t] = my;
        sp.al[t] = -0.5f * L * cyy * invd;
        sp.be[t] =  0.5f * L * (cxy + cyx) * invd;
        sp.ga[t] = -0.5f * L * cxx * invd;
        sp.f0[t] = -log2f(6.283185307179586f * sqrtf(det));
    }
    __syncthreads();

    int tx = threadIdx.x;   // 0..15 : t-group (4 consecutive t)
    int ty = threadIdx.y;   // 0..15 : y stripe

    // Conflict-free float4 loads: lane addresses are consecutive 16B chunks.
    float4 mx4 = *(const float4*)&sp.mx[4 * tx];
    float4 my4 = *(const float4*)&sp.my[4 * tx];
    float4 al4 = *(const float4*)&sp.al[4 * tx];
    float4 be4 = *(const float4*)&sp.be[4 * tx];
    float4 ga4 = *(const float4*)&sp.ga[4 * tx];
    float4 f04 = *(const float4*)&sp.f0[4 * tx];

    float mxj[4] = {mx4.x, mx4.y, mx4.z, mx4.w};
    float myj[4] = {my4.x, my4.y, my4.z, my4.w};
    float alj[4] = {al4.x, al4.y, al4.z, al4.w};
    float bej[4] = {be4.x, be4.y, be4.z, be4.w};
    float gaj[4] = {ga4.x, ga4.y, ga4.z, ga4.w};
    float f0j[4] = {f04.x, f04.y, f04.z, f04.w};

    // Output base in float4 units for xi=0: (((b*64 + x0)*64 + 0)*64 + 4*tx)/4
    float4* ob0 = (float4*)out
                + (size_t)((b * MAP_W + x0) * MAP_H) * (T_SIZE / 4) + tx;

    #pragma unroll
    for (int xi = 0; xi < XPB; ++xi) {
        // Per-column constants (8 live regs, recomputed per xi to bound pressure)
        float Q[4], P[4];
        float xf = (float)(x0 + xi);
        #pragma unroll
        for (int j = 0; j < 4; ++j) {
            float dx = xf - mxj[j];
            Q[j] = bej[j] * dx;                     // be*dx
            P[j] = fmaf(alj[j] * dx, dx, f0j[j]);   // al*dx^2 + f0
        }

        float4* ob = ob0 + (size_t)xi * MAP_H * (T_SIZE / 4);
        #pragma unroll
        for (int i = 0; i < 4; ++i) {
            int   yy = ty + 16 * i;
            float yf = (float)yy;
            float4 r;
            {
                float dy = yf - myj[0];
                r.x = ex2_approx(fmaf(dy, fmaf(gaj[0], dy, Q[0]), P[0]));
            }
            {
                float dy = yf - myj[1];
                r.y = ex2_approx(fmaf(dy, fmaf(gaj[1], dy, Q[1]), P[1]));
            }
            {
                float dy = yf - myj[2];
                r.z = ex2_approx(fmaf(dy, fmaf(gaj[2], dy, Q[2]), P[2]));
            }
            {
                float dy = yf - myj[3];
                r.w = ex2_approx(fmaf(dy, fmaf(gaj[3], dy, Q[3]), P[3]));
            }
            __stcs(ob + (size_t)yy * (T_SIZE / 4), r);
        }
    }
}

extern "C" void kernel_launch(void* const* d_in, const int* in_sizes, int n_in,
                              void* d_out, int out_size) {
    const float* cp_means = (const float*)d_in[0];
    const int*   num_cps  = (const int*)d_in[1];
    const float* cp_cov   = (const float*)d_in[2];
    float*       out      = (float*)d_out;

    dim3 block(16, 16);
    dim3 grid(MAP_W / XPB, BATCH);
    map_kernel<<<grid, block>>>(cp_means, num_cps, cp_cov, out);
}

// round 9
// speedup vs baseline: 1.9987x; 1.9987x over previous
#include <cuda_runtime.h>

#define MAP_W  64
#define MAP_H  64
#define T_SIZE 64
#define NUM_CP 8
#define BATCH  128
#define XPB    2      // x-columns per block

__device__ __forceinline__ float ex2_approx(float x) {
    float r;
    asm("ex2.approx.f32 %0, %1;" : "=f"(r) : "f"(x));
    return r;
}

// Fused kernel: block = (b, pair of x columns). Threads 0..63 compute the
// per-(b,t) Gaussian params for all 64 t into shared memory (SoA layout so
// the consumer float4 loads are bank-conflict-free), then all 256 threads
// stream 2 * 64*64 (y,t) tiles of exp2 evaluations.
//
// exponent(dx,dy) = al*dx^2 + be*dx*dy + ga*dy^2 + f0  (log2 domain; f0
// includes log2 of the normalizer), output = exp2(exponent).
struct SoAParams {
    float mx[T_SIZE], my[T_SIZE], al[T_SIZE],
          be[T_SIZE], ga[T_SIZE], f0[T_SIZE];
};

__global__ __launch_bounds__(256)
void map_kernel(const float* __restrict__ cp_means,
                const int*   __restrict__ num_cps,
                const float* __restrict__ cp_cov,
                float*       __restrict__ out) {
    __shared__ SoAParams sp;

    int x0  = blockIdx.x * XPB;                // 0,2,..,62
    int b   = blockIdx.y;                      // 0..127
    int tid = threadIdx.y * 16 + threadIdx.x;  // 0..255

    if (tid < T_SIZE) {
        int   t  = tid;
        float tf = (float)t * (1.0f / 63.0f);
        float u  = 1.0f - tf;
        int   n  = __ldg(num_cps + b) - 1;     // 2..7

        // Bernstein weights via de Casteljau (exact, register-resident).
        float w[NUM_CP];
        w[0] = 1.0f;
        #pragma unroll
        for (int k = 1; k < NUM_CP; ++k) w[k] = 0.0f;
        #pragma unroll
        for (int m = 1; m < NUM_CP; ++m) {
            if (m <= n) {
                #pragma unroll
                for (int k = NUM_CP - 1; k >= 1; --k)
                    w[k] = u * w[k] + tf * w[k - 1];
                w[0] = u * w[0];
            }
        }

        float mx = 0.f, my = 0.f, cxx = 0.f, cxy = 0.f, cyx = 0.f, cyy = 0.f;
        #pragma unroll
        for (int k = 0; k < NUM_CP; ++k) {
            float wk = w[k];
            float2 m = __ldg((const float2*)(cp_means + (k * BATCH + b) * 2));
            mx += wk * m.x;
            my += wk * m.y;
            float w2 = wk * wk;
            float4 cv = __ldg((const float4*)(cp_cov + (k * BATCH + b) * 4));
            cxx += w2 * cv.x;  cxy += w2 * cv.y;
            cyx += w2 * cv.z;  cyy += w2 * cv.w;
        }

        float det  = cxx * cyy - cxy * cyx;
        float invd = 1.0f / det;
        const float L = 1.4426950408889634f;   // log2(e)
        sp.mx[t] = mx;
        sp.my[t] = my;
        sp.al[t] = -0.5f * L * cyy * invd;
        sp.be[t] =  0.5f * L * (cxy + cyx) * invd;
        sp.ga[t] = -0.5f * L * cxx * invd;
        sp.f0[t] = -log2f(6.283185307179586f * sqrtf(det));
    }
    __syncthreads();

    int tx = threadIdx.x;   // 0..15 : t-group (4 consecutive t)
    int ty = threadIdx.y;   // 0..15 : y stripe

    // Conflict-free float4 loads: lane addresses are consecutive 16B chunks.
    float4 mx4 = *(const float4*)&sp.mx[4 * tx];
    float4 my4 = *(const float4*)&sp.my[4 * tx];
    float4 al4 = *(const float4*)&sp.al[4 * tx];
    float4 be4 = *(const float4*)&sp.be[4 * tx];
    float4 ga4 = *(const float4*)&sp.ga[4 * tx];
    float4 f04 = *(const float4*)&sp.f0[4 * tx];

    float mxj[4] = {mx4.x, mx4.y, mx4.z, mx4.w};
    float myj[4] = {my4.x, my4.y, my4.z, my4.w};
    float alj[4] = {al4.x, al4.y, al4.z, al4.w};
    float bej[4] = {be4.x, be4.y, be4.z, be4.w};
    float gaj[4] = {ga4.x, ga4.y, ga4.z, ga4.w};
    float f0j[4] = {f04.x, f04.y, f04.z, f04.w};

    float Q[XPB][4], P[XPB][4];
    #pragma unroll
    for (int j = 0; j < 4; ++j) {
        #pragma unroll
        for (int xi = 0; xi < XPB; ++xi) {
            float dx = (float)(x0 + xi) - mxj[j];
            Q[xi][j] = bej[j] * dx;                     // be*dx
            P[xi][j] = fmaf(alj[j] * dx, dx, f0j[j]);   // al*dx^2 + f0
        }
    }

    #pragma unroll
    for (int xi = 0; xi < XPB; ++xi) {
        // Output base in float4 units: (((b*64 + x)*64 + y)*64 + 4*tx)/4
        float4* ob = (float4*)out
                   + (size_t)((b * MAP_W + (x0 + xi)) * MAP_H) * (T_SIZE / 4) + tx;
        #pragma unroll
        for (int i = 0; i < 4; ++i) {
            int   yy = ty + 16 * i;
            float yf = (float)yy;
            float4 r;
            {
                float dy = yf - myj[0];
                r.x = ex2_approx(fmaf(dy, fmaf(gaj[0], dy, Q[xi][0]), P[xi][0]));
            }
            {
                float dy = yf - myj[1];
                r.y = ex2_approx(fmaf(dy, fmaf(gaj[1], dy, Q[xi][1]), P[xi][1]));
            }
            {
                float dy = yf - myj[2];
                r.z = ex2_approx(fmaf(dy, fmaf(gaj[2], dy, Q[xi][2]), P[xi][2]));
            }
            {
                float dy = yf - myj[3];
                r.w = ex2_approx(fmaf(dy, fmaf(gaj[3], dy, Q[xi][3]), P[xi][3]));
            }
            __stcs(ob + (size_t)yy * (T_SIZE / 4), r);
        }
    }
}

extern "C" void kernel_launch(void* const* d_in, const int* in_sizes, int n_in,
                              void* d_out, int out_size) {
    const float* cp_means = (const float*)d_in[0];
    const int*   num_cps  = (const int*)d_in[1];
    const float* cp_cov   = (const float*)d_in[2];
    float*       out      = (float*)d_out;

    dim3 block(16, 16);
    dim3 grid(MAP_W / XPB, BATCH);
    map_kernel<<<grid, block>>>(cp_means, num_cps, cp_cov, out);
}